// round 4
// baseline (speedup 1.0000x reference)
#include <cuda_runtime.h>
#include <cuda_fp16.h>

#define D_IN  128
#define D_OUT 64
#define TM    64
#define MAX_NODES 50000

// scratch: h = x @ W stored fp16 (50000 x 64 = 6.4 MB), CSR row pointers
__device__ __half g_h[MAX_NODES * D_OUT];
__device__ int    g_row_ptr[MAX_NODES + 1];

// ---------------------------------------------------------------------------
// CSR row offsets via boundary detection, 4 edges per thread (int4).
// row_ptr[i] = first e with dst[e] >= i.
// ---------------------------------------------------------------------------
__global__ void rowptr_kernel(const int* __restrict__ dst,
                              int n_edges, int n_nodes) {
    int t = blockIdx.x * blockDim.x + threadIdx.x;
    int e = t << 2;
    if (e >= n_edges) return;

    int d[5];
    d[0] = (e == 0) ? -1 : __ldg(dst + e - 1);
    if (e + 3 < n_edges) {
        int4 q = *(const int4*)(dst + e);
        d[1] = q.x; d[2] = q.y; d[3] = q.z; d[4] = q.w;
    } else {
        #pragma unroll
        for (int j = 0; j < 4; j++)
            d[j + 1] = (e + j < n_edges) ? __ldg(dst + e + j) : d[j];
    }

    #pragma unroll
    for (int j = 0; j < 4; j++) {
        int ee = e + j;
        if (ee < n_edges)
            for (int i = d[j] + 1; i <= d[j + 1]; i++) g_row_ptr[i] = ee;
    }
    if (e + 4 >= n_edges) {  // tail nodes past the last dst
        int last = d[4];
        for (int i = last + 1; i <= n_nodes; i++) g_row_ptr[i] = n_edges;
    }
}

// ---------------------------------------------------------------------------
// h = x @ W with packed fp32 (fma.rn.f32x2).  TM=64 rows/block, 128 threads.
// Xs transposed [k][row]: adjacent rows adjacent in smem -> row-pairs load
// as a single 64-bit value, used directly as f32x2 operands.
// Each thread: 8 rows (4 pairs) x 4 cols.  Epilogue stores h as fp16.
// ---------------------------------------------------------------------------
__global__ void __launch_bounds__(128)
gemm_kernel(const float* __restrict__ x,
            const float* __restrict__ w,
            int n_nodes) {
    __shared__ float Xs[D_IN][TM];   // 32 KB

    int tid  = threadIdx.x;
    int row0 = blockIdx.x * TM;

    for (int i = tid; i < TM * (D_IN / 4); i += 128) {
        int r  = i >> 5;
        int kq = (i & 31) << 2;
        int gr = row0 + r;
        float4 v = make_float4(0.f, 0.f, 0.f, 0.f);
        if (gr < n_nodes)
            v = *(const float4*)(x + (size_t)gr * D_IN + kq);
        Xs[kq + 0][r] = v.x;
        Xs[kq + 1][r] = v.y;
        Xs[kq + 2][r] = v.z;
        Xs[kq + 3][r] = v.w;
    }
    __syncthreads();

    int cg = (tid & 15) << 2;   // column base (4 cols)
    int rg = (tid >> 4) << 3;   // row base    (8 rows = 4 pairs)

    unsigned long long acc[4][4];   // [row-pair][col], packed f32x2
    #pragma unroll
    for (int jp = 0; jp < 4; jp++)
        #pragma unroll
        for (int c = 0; c < 4; c++) acc[jp][c] = 0ull;

    #pragma unroll 4
    for (int k = 0; k < D_IN; k++) {
        float4 wv = __ldg((const float4*)(w + k * D_OUT + cg));
        unsigned long long bb[4];
        asm("mov.b64 %0, {%1,%1};" : "=l"(bb[0]) : "f"(wv.x));
        asm("mov.b64 %0, {%1,%1};" : "=l"(bb[1]) : "f"(wv.y));
        asm("mov.b64 %0, {%1,%1};" : "=l"(bb[2]) : "f"(wv.z));
        asm("mov.b64 %0, {%1,%1};" : "=l"(bb[3]) : "f"(wv.w));

        unsigned long long ap[4];
        ap[0] = *(const unsigned long long*)(&Xs[k][rg + 0]);
        ap[1] = *(const unsigned long long*)(&Xs[k][rg + 2]);
        ap[2] = *(const unsigned long long*)(&Xs[k][rg + 4]);
        ap[3] = *(const unsigned long long*)(&Xs[k][rg + 6]);

        #pragma unroll
        for (int jp = 0; jp < 4; jp++)
            #pragma unroll
            for (int c = 0; c < 4; c++)
                asm("fma.rn.f32x2 %0, %1, %2, %0;"
                    : "+l"(acc[jp][c]) : "l"(ap[jp]), "l"(bb[c]));
    }

    #pragma unroll
    for (int jp = 0; jp < 4; jp++) {
        float lo[4], hi[4];
        #pragma unroll
        for (int c = 0; c < 4; c++)
            asm("mov.b64 {%0,%1}, %2;" : "=f"(lo[c]), "=f"(hi[c]) : "l"(acc[jp][c]));

        int r0 = row0 + rg + 2 * jp;
        if (r0 < n_nodes) {
            union { __half2 h2[2]; uint2 u; } pk;
            pk.h2[0] = __floats2half2_rn(lo[0], lo[1]);
            pk.h2[1] = __floats2half2_rn(lo[2], lo[3]);
            *(uint2*)(g_h + (size_t)r0 * D_OUT + cg) = pk.u;
        }
        if (r0 + 1 < n_nodes) {
            union { __half2 h2[2]; uint2 u; } pk;
            pk.h2[0] = __floats2half2_rn(hi[0], hi[1]);
            pk.h2[1] = __floats2half2_rn(hi[2], hi[3]);
            *(uint2*)(g_h + (size_t)(r0 + 1) * D_OUT + cg) = pk.u;
        }
    }
}

// ---------------------------------------------------------------------------
// Warp-per-node aggregation.  Lane c owns cols [2c,2c+1] (one half2 = 4 B,
// so a full h-row gather is exactly one 128 B line).  src/vals are loaded
// coalesced by lanes 0..7 and shuffle-broadcast; 8 h-gathers issued
// back-to-back per group for MLP=8.  No atomics; bias fused.
// ---------------------------------------------------------------------------
__global__ void __launch_bounds__(256)
gather_kernel(const int*   __restrict__ src,
              const float* __restrict__ vals,
              const float* __restrict__ bias,
              float*       __restrict__ out,
              int n_nodes) {
    int gwarp = (blockIdx.x * 256 + threadIdx.x) >> 5;
    int lane  = threadIdx.x & 31;
    if (gwarp >= n_nodes) return;

    int e0 = g_row_ptr[gwarp];
    int e1 = g_row_ptr[gwarp + 1];

    float accx = 0.f, accy = 0.f;

    for (int base = e0; base < e1; base += 8) {
        int n = e1 - base; if (n > 8) n = 8;
        int idx = base + (lane & 7);
        if (idx >= e1) idx = e1 - 1;
        int   sv = __ldg(src  + idx);
        float vv = __ldg(vals + idx);

        int   s[8];
        float v[8];
        #pragma unroll
        for (int j = 0; j < 8; j++) {
            s[j] = __shfl_sync(0xffffffffu, sv, j);
            v[j] = (j < n) ? __shfl_sync(0xffffffffu, vv, j) : 0.f;
        }

        __half2 hh[8];
        #pragma unroll
        for (int j = 0; j < 8; j++)
            hh[j] = *(const __half2*)(g_h + ((size_t)s[j] << 6) + (lane << 1));

        #pragma unroll
        for (int j = 0; j < 8; j++) {
            float2 hf = __half22float2(hh[j]);
            accx += v[j] * hf.x;
            accy += v[j] * hf.y;
        }
    }

    float2 b = __ldg((const float2*)bias + lane);
    ((float2*)out)[(size_t)gwarp * 32 + lane] = make_float2(accx + b.x, accy + b.y);
}

// ---------------------------------------------------------------------------
extern "C" void kernel_launch(void* const* d_in, const int* in_sizes, int n_in,
                              void* d_out, int out_size) {
    const float* x     = (const float*)d_in[0];
    const int*   esrc  = (const int*)  d_in[1];
    const int*   edst  = (const int*)  d_in[2];
    const float* evals = (const float*)d_in[3];
    const float* w     = (const float*)d_in[4];
    const float* bias  = (const float*)d_in[5];
    float*       out   = (float*)d_out;

    int n_nodes = in_sizes[0] / D_IN;
    int n_edges = in_sizes[1];

    int nt = (n_edges + 3) / 4;
    rowptr_kernel<<<(nt + 255) / 256, 256>>>(edst, n_edges, n_nodes);

    gemm_kernel<<<(n_nodes + TM - 1) / TM, 128>>>(x, w, n_nodes);

    gather_kernel<<<(n_nodes * 32 + 255) / 256, 256>>>(esrc, evals, bias, out, n_nodes);
}

// round 5
// speedup vs baseline: 1.2891x; 1.2891x over previous
#include <cuda_runtime.h>
#include <cuda_fp16.h>

#define D_IN  128
#define D_OUT 64
#define TM    64
#define MAX_NODES 50000

// scratch: h = x @ W stored fp16 (6.4 MB), CSR row pointers
__device__ __half g_h[MAX_NODES * D_OUT];
__device__ int    g_row_ptr[MAX_NODES + 1];

// ---------------------------------------------------------------------------
// CSR row offsets via boundary detection, 16 edges per thread (4x int4, MLP=4).
// row_ptr[i] = first e with dst[e] >= i.
// ---------------------------------------------------------------------------
__global__ void rowptr_kernel(const int* __restrict__ dst,
                              int n_edges, int n_nodes) {
    int t  = blockIdx.x * blockDim.x + threadIdx.x;
    int e0 = t << 4;
    if (e0 >= n_edges) return;

    int d[17];
    d[0] = (e0 == 0) ? -1 : __ldg(dst + e0 - 1);

    if (e0 + 16 <= n_edges) {
        int4 q0 = __ldg((const int4*)(dst + e0));
        int4 q1 = __ldg((const int4*)(dst + e0 + 4));
        int4 q2 = __ldg((const int4*)(dst + e0 + 8));
        int4 q3 = __ldg((const int4*)(dst + e0 + 12));
        d[1]=q0.x; d[2]=q0.y; d[3]=q0.z; d[4]=q0.w;
        d[5]=q1.x; d[6]=q1.y; d[7]=q1.z; d[8]=q1.w;
        d[9]=q2.x; d[10]=q2.y; d[11]=q2.z; d[12]=q2.w;
        d[13]=q3.x; d[14]=q3.y; d[15]=q3.z; d[16]=q3.w;
    } else {
        #pragma unroll
        for (int j = 0; j < 16; j++)
            d[j + 1] = (e0 + j < n_edges) ? __ldg(dst + e0 + j) : d[j];
    }

    #pragma unroll
    for (int j = 0; j < 16; j++) {
        int ee = e0 + j;
        if (ee < n_edges)
            for (int i = d[j] + 1; i <= d[j + 1]; i++) g_row_ptr[i] = ee;
    }
    if (e0 + 16 >= n_edges) {
        int last = d[16];
        for (int i = last + 1; i <= n_nodes; i++) g_row_ptr[i] = n_edges;
    }
}

// ---------------------------------------------------------------------------
// h = x @ W, packed f32x2 FMA, CONFLICT-FREE swizzled x-tile.
// Logical Xs[k][col] stored at column col ^ SW(k), SW(k) = ((k>>2)&15)<<2.
// Store: 32 lanes hit 16 distinct banks (2-way) instead of 1 (32-way).
// Compute: reads are warp-broadcast; swizzle adds one LOP per k.
// Each thread: 8 rows (4 f32x2 pairs) x 4 cols.  Epilogue stores h as fp16.
// ---------------------------------------------------------------------------
__global__ void __launch_bounds__(128)
gemm_kernel(const float* __restrict__ x,
            const float* __restrict__ w,
            int n_nodes) {
    __shared__ float Xs[D_IN][TM];   // 32 KB, swizzled columns

    int tid  = threadIdx.x;
    int row0 = blockIdx.x * TM;

    for (int i = tid; i < TM * (D_IN / 4); i += 128) {
        int r  = i >> 5;            // logical column (node row in tile)
        int kq = (i & 31) << 2;     // k base
        int gr = row0 + r;
        float4 v = make_float4(0.f, 0.f, 0.f, 0.f);
        if (gr < n_nodes)
            v = *(const float4*)(x + (size_t)gr * D_IN + kq);
        int sw = ((kq >> 2) & 15) << 2;   // same for kq..kq+3
        int rc = r ^ sw;
        Xs[kq + 0][rc] = v.x;
        Xs[kq + 1][rc] = v.y;
        Xs[kq + 2][rc] = v.z;
        Xs[kq + 3][rc] = v.w;
    }
    __syncthreads();

    int cg = (tid & 15) << 2;   // output column base (4 cols)
    int rg = (tid >> 4) << 3;   // row base (8 rows = 4 pairs)

    unsigned long long acc[4][4];
    #pragma unroll
    for (int jp = 0; jp < 4; jp++)
        #pragma unroll
        for (int c = 0; c < 4; c++) acc[jp][c] = 0ull;

    #pragma unroll 2
    for (int k = 0; k < D_IN; k++) {
        float4 wv = __ldg((const float4*)(w + k * D_OUT + cg));
        unsigned long long bb[4];
        asm("mov.b64 %0, {%1,%1};" : "=l"(bb[0]) : "f"(wv.x));
        asm("mov.b64 %0, {%1,%1};" : "=l"(bb[1]) : "f"(wv.y));
        asm("mov.b64 %0, {%1,%1};" : "=l"(bb[2]) : "f"(wv.z));
        asm("mov.b64 %0, {%1,%1};" : "=l"(bb[3]) : "f"(wv.w));

        int sw = ((k >> 2) & 15) << 2;
        unsigned long long ap[4];
        ap[0] = *(const unsigned long long*)(&Xs[k][(rg + 0) ^ sw]);
        ap[1] = *(const unsigned long long*)(&Xs[k][(rg + 2) ^ sw]);
        ap[2] = *(const unsigned long long*)(&Xs[k][(rg + 4) ^ sw]);
        ap[3] = *(const unsigned long long*)(&Xs[k][(rg + 6) ^ sw]);

        #pragma unroll
        for (int jp = 0; jp < 4; jp++)
            #pragma unroll
            for (int c = 0; c < 4; c++)
                asm("fma.rn.f32x2 %0, %1, %2, %0;"
                    : "+l"(acc[jp][c]) : "l"(ap[jp]), "l"(bb[c]));
    }

    #pragma unroll
    for (int jp = 0; jp < 4; jp++) {
        float lo[4], hi[4];
        #pragma unroll
        for (int c = 0; c < 4; c++)
            asm("mov.b64 {%0,%1}, %2;" : "=f"(lo[c]), "=f"(hi[c]) : "l"(acc[jp][c]));

        int r0 = row0 + rg + 2 * jp;
        if (r0 < n_nodes) {
            union { __half2 h2[2]; uint2 u; } pk;
            pk.h2[0] = __floats2half2_rn(lo[0], lo[1]);
            pk.h2[1] = __floats2half2_rn(lo[2], lo[3]);
            *(uint2*)(g_h + (size_t)r0 * D_OUT + cg) = pk.u;
        }
        if (r0 + 1 < n_nodes) {
            union { __half2 h2[2]; uint2 u; } pk;
            pk.h2[0] = __floats2half2_rn(hi[0], hi[1]);
            pk.h2[1] = __floats2half2_rn(hi[2], hi[3]);
            *(uint2*)(g_h + (size_t)(r0 + 1) * D_OUT + cg) = pk.u;
        }
    }
}

// ---------------------------------------------------------------------------
// Warp-per-node aggregation.  Lane c owns cols [2c,2c+1] (half2 = 4 B ->
// one 128 B line per h-row gather).  src/vals read as warp-uniform
// broadcasts; 8 gathers hoisted per group for MLP=8.  No atomics.
// ---------------------------------------------------------------------------
__global__ void __launch_bounds__(256)
gather_kernel(const int*   __restrict__ src,
              const float* __restrict__ vals,
              const float* __restrict__ bias,
              float*       __restrict__ out,
              int n_nodes) {
    int gwarp = (blockIdx.x * 256 + threadIdx.x) >> 5;
    int lane  = threadIdx.x & 31;
    if (gwarp >= n_nodes) return;

    int e0 = g_row_ptr[gwarp];
    int e1 = g_row_ptr[gwarp + 1];

    float accx = 0.f, accy = 0.f;

    int e = e0;
    for (; e + 8 <= e1; e += 8) {
        int s[8]; float v[8];
        #pragma unroll
        for (int j = 0; j < 8; j++) { s[j] = __ldg(src + e + j); v[j] = __ldg(vals + e + j); }
        __half2 hh[8];
        #pragma unroll
        for (int j = 0; j < 8; j++)
            hh[j] = *(const __half2*)(g_h + ((size_t)s[j] << 6) + (lane << 1));
        #pragma unroll
        for (int j = 0; j < 8; j++) {
            float2 hf = __half22float2(hh[j]);
            accx += v[j] * hf.x;
            accy += v[j] * hf.y;
        }
    }
    for (; e < e1; e++) {
        int   sv = __ldg(src + e);
        float vv = __ldg(vals + e);
        float2 hf = __half22float2(*(const __half2*)(g_h + ((size_t)sv << 6) + (lane << 1)));
        accx += vv * hf.x;
        accy += vv * hf.y;
    }

    float2 b = __ldg((const float2*)bias + lane);
    ((float2*)out)[(size_t)gwarp * 32 + lane] = make_float2(accx + b.x, accy + b.y);
}

// ---------------------------------------------------------------------------
extern "C" void kernel_launch(void* const* d_in, const int* in_sizes, int n_in,
                              void* d_out, int out_size) {
    const float* x     = (const float*)d_in[0];
    const int*   esrc  = (const int*)  d_in[1];
    const int*   edst  = (const int*)  d_in[2];
    const float* evals = (const float*)d_in[3];
    const float* w     = (const float*)d_in[4];
    const float* bias  = (const float*)d_in[5];
    float*       out   = (float*)d_out;

    int n_nodes = in_sizes[0] / D_IN;
    int n_edges = in_sizes[1];

    // gemm first (independent of rowptr) -> rotates ncu's captured slot
    gemm_kernel<<<(n_nodes + TM - 1) / TM, 128>>>(x, w, n_nodes);

    int nt = (n_edges + 15) / 16;
    rowptr_kernel<<<(nt + 255) / 256, 256>>>(edst, n_edges, n_nodes);

    gather_kernel<<<(n_nodes * 32 + 255) / 256, 256>>>(esrc, evals, bias, out, n_nodes);
}

// round 8
// speedup vs baseline: 1.5989x; 1.2403x over previous
#include <cuda_runtime.h>
#include <cuda_fp16.h>

#define D_IN  128
#define D_OUT 64
#define MAX_NODES 50000
#define RPB 128   // rows per block (gemm)
#define RPW 32    // rows per warp

// scratch: h = x @ W stored fp16 (6.4 MB), CSR row pointers
__device__ __half g_h[MAX_NODES * D_OUT];
__device__ int    g_row_ptr[MAX_NODES + 1];

// ---------------------------------------------------------------------------
// CSR row offsets via boundary detection, 16 edges per thread (4x int4, MLP=4).
// ---------------------------------------------------------------------------
__global__ void rowptr_kernel(const int* __restrict__ dst,
                              int n_edges, int n_nodes) {
    int t  = blockIdx.x * blockDim.x + threadIdx.x;
    int e0 = t << 4;
    if (e0 >= n_edges) return;

    int d[17];
    d[0] = (e0 == 0) ? -1 : __ldg(dst + e0 - 1);

    if (e0 + 16 <= n_edges) {
        int4 q0 = __ldg((const int4*)(dst + e0));
        int4 q1 = __ldg((const int4*)(dst + e0 + 4));
        int4 q2 = __ldg((const int4*)(dst + e0 + 8));
        int4 q3 = __ldg((const int4*)(dst + e0 + 12));
        d[1]=q0.x; d[2]=q0.y; d[3]=q0.z; d[4]=q0.w;
        d[5]=q1.x; d[6]=q1.y; d[7]=q1.z; d[8]=q1.w;
        d[9]=q2.x; d[10]=q2.y; d[11]=q2.z; d[12]=q2.w;
        d[13]=q3.x; d[14]=q3.y; d[15]=q3.z; d[16]=q3.w;
    } else {
        #pragma unroll
        for (int j = 0; j < 16; j++)
            d[j + 1] = (e0 + j < n_edges) ? __ldg(dst + e0 + j) : d[j];
    }

    #pragma unroll
    for (int j = 0; j < 16; j++) {
        int ee = e0 + j;
        if (ee < n_edges)
            for (int i = d[j] + 1; i <= d[j + 1]; i++) g_row_ptr[i] = ee;
    }
    if (e0 + 16 >= n_edges) {
        int last = d[16];
        for (int i = last + 1; i <= n_nodes; i++) g_row_ptr[i] = n_edges;
    }
}

// ---------------------------------------------------------------------------
// h = x @ W on tensor cores: mma.sync.m16n8k8 tf32, fp32 accumulate.
// Block = 128 threads (4 warps), warp = 32 rows x 64 cols, block = 128 rows.
// x tile staged in smem PRE-CONVERTED to tf32, two k-halves of 64 (34.8 KB,
// stride 68 -> fragment LDS bank = 4g+tig, conflict-free).
// W fragments via __ldg (L1-resident) + cvt.  Epilogue stores h as fp16.
// ---------------------------------------------------------------------------
__device__ __forceinline__ unsigned f2tf(float f) {
    unsigned u;
    asm("cvt.rna.tf32.f32 %0, %1;" : "=r"(u) : "f"(f));
    return u;
}

__global__ void __launch_bounds__(128)
gemm_kernel(const float* __restrict__ x,
            const float* __restrict__ w,
            int n_nodes) {
    __shared__ unsigned Xs[RPB][68];   // 34.8 KB

    int tid  = threadIdx.x;
    int lane = tid & 31;
    int warp = tid >> 5;
    int row0 = blockIdx.x * RPB;
    int g    = lane >> 2;      // group id (0..7)
    int tig  = lane & 3;       // thread-in-group
    int wrow = warp * RPW;

    float acc[2][8][4];
    #pragma unroll
    for (int mb = 0; mb < 2; mb++)
        #pragma unroll
        for (int nt = 0; nt < 8; nt++)
            #pragma unroll
            for (int c = 0; c < 4; c++) acc[mb][nt][c] = 0.f;

    #pragma unroll
    for (int half = 0; half < 2; half++) {
        __syncthreads();   // protect Xs being re-read by other warps (half=1)
        // stage 128 rows x 64 k-cols, converted to tf32
        for (int i = tid; i < RPB * 16; i += 128) {
            int r = i >> 4, q = i & 15;
            int gr = row0 + r;
            float4 v = make_float4(0.f, 0.f, 0.f, 0.f);
            if (gr < n_nodes)
                v = __ldg((const float4*)(x + (size_t)gr * D_IN + half * 64 + q * 4));
            uint4 t;
            t.x = f2tf(v.x); t.y = f2tf(v.y); t.z = f2tf(v.z); t.w = f2tf(v.w);
            *(uint4*)&Xs[r][q * 4] = t;
        }
        __syncthreads();

        #pragma unroll
        for (int ks = 0; ks < 8; ks++) {
            int k0 = half * 64 + ks * 8;   // global k
            int sk = ks * 8;               // smem k

            unsigned b[8][2];
            #pragma unroll
            for (int nt = 0; nt < 8; nt++) {
                b[nt][0] = f2tf(__ldg(w + (k0 + tig)     * D_OUT + nt * 8 + g));
                b[nt][1] = f2tf(__ldg(w + (k0 + tig + 4) * D_OUT + nt * 8 + g));
            }

            #pragma unroll
            for (int mb = 0; mb < 2; mb++) {
                unsigned a0 = Xs[wrow + mb * 16 + g    ][sk + tig];
                unsigned a1 = Xs[wrow + mb * 16 + g + 8][sk + tig];
                unsigned a2 = Xs[wrow + mb * 16 + g    ][sk + tig + 4];
                unsigned a3 = Xs[wrow + mb * 16 + g + 8][sk + tig + 4];
                #pragma unroll
                for (int nt = 0; nt < 8; nt++) {
                    asm volatile(
                        "mma.sync.aligned.m16n8k8.row.col.f32.tf32.tf32.f32 "
                        "{%0,%1,%2,%3},{%4,%5,%6,%7},{%8,%9},{%0,%1,%2,%3};"
                        : "+f"(acc[mb][nt][0]), "+f"(acc[mb][nt][1]),
                          "+f"(acc[mb][nt][2]), "+f"(acc[mb][nt][3])
                        : "r"(a0), "r"(a1), "r"(a2), "r"(a3),
                          "r"(b[nt][0]), "r"(b[nt][1]));
                }
            }
        }
    }

    // epilogue: D frag (c0,c1)@(row=g, col=2tig) , (c2,c3)@(row=g+8)
    #pragma unroll
    for (int mb = 0; mb < 2; mb++) {
        int r0 = row0 + wrow + mb * 16 + g;
        #pragma unroll
        for (int nt = 0; nt < 8; nt++) {
            int c0 = nt * 8 + 2 * tig;
            if (r0 < n_nodes)
                *(__half2*)(g_h + (size_t)r0 * D_OUT + c0) =
                    __floats2half2_rn(acc[mb][nt][0], acc[mb][nt][1]);
            if (r0 + 8 < n_nodes)
                *(__half2*)(g_h + (size_t)(r0 + 8) * D_OUT + c0) =
                    __floats2half2_rn(acc[mb][nt][2], acc[mb][nt][3]);
        }
    }
}

// ---------------------------------------------------------------------------
// Warp-per-node aggregation.  Lane c owns cols [2c,2c+1] (half2 = 4 B ->
// one 128 B line per h-row gather).  8 gathers hoisted per group (MLP=8).
// ---------------------------------------------------------------------------
__global__ void __launch_bounds__(256)
gather_kernel(const int*   __restrict__ src,
              const float* __restrict__ vals,
              const float* __restrict__ bias,
              float*       __restrict__ out,
              int n_nodes) {
    int gwarp = (blockIdx.x * 256 + threadIdx.x) >> 5;
    int lane  = threadIdx.x & 31;
    if (gwarp >= n_nodes) return;

    int e0 = g_row_ptr[gwarp];
    int e1 = g_row_ptr[gwarp + 1];

    float accx = 0.f, accy = 0.f;

    int e = e0;
    for (; e + 8 <= e1; e += 8) {
        int s[8]; float v[8];
        #pragma unroll
        for (int j = 0; j < 8; j++) { s[j] = __ldg(src + e + j); v[j] = __ldg(vals + e + j); }
        __half2 hh[8];
        #pragma unroll
        for (int j = 0; j < 8; j++)
            hh[j] = *(const __half2*)(g_h + ((size_t)s[j] << 6) + (lane << 1));
        #pragma unroll
        for (int j = 0; j < 8; j++) {
            float2 hf = __half22float2(hh[j]);
            accx += v[j] * hf.x;
            accy += v[j] * hf.y;
        }
    }
    for (; e < e1; e++) {
        int   sv = __ldg(src + e);
        float vv = __ldg(vals + e);
        float2 hf = __half22float2(*(const __half2*)(g_h + ((size_t)sv << 6) + (lane << 1)));
        accx += vv * hf.x;
        accy += vv * hf.y;
    }

    float2 b = __ldg((const float2*)bias + lane);
    ((float2*)out)[(size_t)gwarp * 32 + lane] = make_float2(accx + b.x, accy + b.y);
}

// ---------------------------------------------------------------------------
extern "C" void kernel_launch(void* const* d_in, const int* in_sizes, int n_in,
                              void* d_out, int out_size) {
    const float* x     = (const float*)d_in[0];
    const int*   esrc  = (const int*)  d_in[1];
    const int*   edst  = (const int*)  d_in[2];
    const float* evals = (const float*)d_in[3];
    const float* w     = (const float*)d_in[4];
    const float* bias  = (const float*)d_in[5];
    float*       out   = (float*)d_out;

    int n_nodes = in_sizes[0] / D_IN;
    int n_edges = in_sizes[1];

    gemm_kernel<<<(n_nodes + RPB - 1) / RPB, 128>>>(x, w, n_nodes);

    int nt = (n_edges + 15) / 16;
    rowptr_kernel<<<(nt + 255) / 256, 256>>>(edst, n_edges, n_nodes);

    gather_kernel<<<(n_nodes * 32 + 255) / 256, 256>>>(esrc, evals, bias, out, n_nodes);
}